// round 9
// baseline (speedup 1.0000x reference)
#include <cuda_runtime.h>
#include <math.h>
#include <stdint.h>

// ---- problem dims ----
#define Tn 4096      // B*S tokens
#define Dn 768
#define Hn 12
#define DHn 64
#define Sn 512
#define Bsz 8
#define En 8
#define Fn 3072
#define TOPK 2

#define BM 128
#define BN 128
#define BK 16

// fragment-native smem layout:
// A: 16 blocks (mb=m/16 [8] x kb=k/8 [2]); block = [lane 0..31][reg 0..3]
//    value (m,k): lane=(m&7)*4+(k&3), reg=((m>>3)&1)+2*((k>>2)&1)
// B: 32 blocks (nb=n/8 [16] x kb=k/8 [2]); block = [lane 0..31][reg 0..1]
//    value (k,n): lane=(n&7)*4+(k&3), reg=(k>>2)&1
#define ABLK 132            // 128 + 4 pad words -> kb pair lands on different banks
#define BBLK 66             // 64 + 2 pad words
#define A_BUF (16 * ABLK)   // 2112 words
#define B_BUF (32 * BBLK)   // 2112 words

// ---- scratch (device globals: allocation-free per harness rules) ----
__device__ float g_h1[Tn * Dn];
__device__ float g_q[Tn * Dn];
__device__ float g_k[Tn * Dn];
__device__ float g_v[Tn * Dn];
__device__ float g_att[Tn * Dn];
__device__ float g_x1[Tn * Dn];
__device__ float g_h2r[Tn * Dn];                  // tf32-rounded (GEMM A)
__device__ float g_h2x[Tn * Dn];                  // exact (routing)
__device__ float g_mid[(size_t)Tn * TOPK * Fn];   // ~100 MB
__device__ float g_eout[Tn * TOPK * Dn];          // ~25 MB
// tf32-rounded weight copies
__device__ float g_wqr[Dn * Dn];
__device__ float g_wkr[Dn * Dn];
__device__ float g_wvr[Dn * Dn];
__device__ float g_wor[Dn * Dn];
__device__ float g_w1r[(size_t)En * Dn * Fn];     // 72 MB
__device__ float g_w2r[(size_t)En * Fn * Dn];     // 72 MB
__device__ int   g_idx[Tn * TOPK];
__device__ float g_gate[Tn * TOPK];
__device__ int   g_pos[Tn * TOPK];
__device__ int   g_slotof[Tn * TOPK];
__device__ int   g_slot2tok[Tn * TOPK];
__device__ int   g_counts[En];
__device__ int   g_offsets[En];

// ---- helpers ----
__device__ __forceinline__ float gelu_tanh(float x) {
    const float c = 0.7978845608028654f;   // sqrt(2/pi)
    float t = tanhf(c * (x + 0.044715f * x * x * x));
    return 0.5f * x * (1.0f + t);
}

__device__ __forceinline__ uint32_t f2tf(float x) {
    uint32_t r;
    asm("cvt.rna.tf32.f32 %0, %1;" : "=r"(r) : "f"(x));
    return r;
}
__device__ __forceinline__ float roundtf(float x) { return __uint_as_float(f2tf(x)); }

__device__ __forceinline__ void mma_tf32(float* cc,
    uint32_t a0, uint32_t a1, uint32_t a2, uint32_t a3,
    uint32_t b0, uint32_t b1) {
    asm volatile(
        "mma.sync.aligned.m16n8k8.row.col.f32.tf32.tf32.f32 "
        "{%0,%1,%2,%3},{%4,%5,%6,%7},{%8,%9},{%0,%1,%2,%3};"
        : "+f"(cc[0]), "+f"(cc[1]), "+f"(cc[2]), "+f"(cc[3])
        : "r"(a0), "r"(a1), "r"(a2), "r"(a3), "r"(b0), "r"(b1));
}

// ---------------------------------------------------------------------------
// tf32 tensor-core GEMM core, fragment-native smem layout.
// 128x128 tile, BK=16, 256 threads (8 warps), warp tile 64x32
// (4 Mfrags x 4 Nfrags of m16n8k8), fp32 accumulate.
// Operands PRE-ROUNDED to tf32; staging is a raw copy (no cvt in loop).
// Double-buffered, register-staged prefetch, ONE __syncthreads per K-tile.
// Compute-side fragment loads: A = 1x LDS.128, B = 1x LDS.64 (conflict-free).
// Staging (per thread, per K-tile):
//   A: row=t>>1, k=(t&1)*8 .. +7 : 2x LDG.128, 8x scalar STS
//   B: krow=t>>4, n=(t&15)*8 .. +7 : 2x LDG.128, 8x scalar STS
// ---------------------------------------------------------------------------
__device__ __forceinline__ void gemm_core_frag(
    const float* __restrict__ aptr,   // A: thread row base + akc
    const float* __restrict__ bptr,   // B: base + bkrow*ldb + bn + bnc
    int ldb, int iters,
    float (&acc)[16][4],
    float* __restrict__ Asm, float* __restrict__ Bsm,
    int t, int lane, int m0base, int n0base)
{
    // staging offsets (fragment-permuted)
    int arow = t >> 1, akc = (t & 1) * 8;
    int aoff = ((arow >> 4) * 2 + (akc >> 3)) * ABLK
             + ((arow & 7) * 4) * 4 + ((arow >> 3) & 1);
    int bkrow = t >> 4, bnc = (t & 15) * 8;
    int boff = ((bnc >> 3) * 2 + (bkrow >> 3)) * BBLK
             + (bkrow & 3) * 2 + ((bkrow >> 2) & 1);
    int mb0 = m0base >> 4;   // 0 or 4
    int nb0 = n0base >> 3;   // 0,4,8,12

    float4 ra0 = *(const float4*)(aptr);
    float4 ra1 = *(const float4*)(aptr + 4);
    float4 rb0 = *(const float4*)(bptr);
    float4 rb1 = *(const float4*)(bptr + 4);
    {
        float* ab = Asm + aoff;
        ab[0] = ra0.x; ab[4]  = ra0.y; ab[8]  = ra0.z; ab[12] = ra0.w;
        ab[2] = ra1.x; ab[6]  = ra1.y; ab[10] = ra1.z; ab[14] = ra1.w;
        float* bb = Bsm + boff;
        bb[0]  = rb0.x; bb[8]  = rb0.y; bb[16] = rb0.z; bb[24] = rb0.w;
        bb[32] = rb1.x; bb[40] = rb1.y; bb[48] = rb1.z; bb[56] = rb1.w;
    }
    __syncthreads();

    int buf = 0;
    for (int it = 0; it < iters; it++) {
        if (it + 1 < iters) {
            const float* ap = aptr + (it + 1) * BK;
            ra0 = *(const float4*)(ap);
            ra1 = *(const float4*)(ap + 4);
            const float* bp = bptr + (size_t)(it + 1) * BK * ldb;
            rb0 = *(const float4*)(bp);
            rb1 = *(const float4*)(bp + 4);
        }
        const float* Ab = Asm + buf * A_BUF;
        const float* Bb = Bsm + buf * B_BUF;
        #pragma unroll
        for (int kb = 0; kb < 2; kb++) {
            float2 bfr[4];
            #pragma unroll
            for (int nf = 0; nf < 4; nf++)
                bfr[nf] = *(const float2*)(Bb + ((nb0 + nf) * 2 + kb) * BBLK + lane * 2);
            #pragma unroll
            for (int mf = 0; mf < 4; mf++) {
                float4 afr = *(const float4*)(Ab + ((mb0 + mf) * 2 + kb) * ABLK + lane * 4);
                uint32_t fa0 = __float_as_uint(afr.x);
                uint32_t fa1 = __float_as_uint(afr.y);
                uint32_t fa2 = __float_as_uint(afr.z);
                uint32_t fa3 = __float_as_uint(afr.w);
                #pragma unroll
                for (int nf = 0; nf < 4; nf++)
                    mma_tf32(acc[mf * 4 + nf], fa0, fa1, fa2, fa3,
                             __float_as_uint(bfr[nf].x), __float_as_uint(bfr[nf].y));
            }
        }
        if (it + 1 < iters) {
            float* ab = Asm + (buf ^ 1) * A_BUF + aoff;
            ab[0] = ra0.x; ab[4]  = ra0.y; ab[8]  = ra0.z; ab[12] = ra0.w;
            ab[2] = ra1.x; ab[6]  = ra1.y; ab[10] = ra1.z; ab[14] = ra1.w;
            float* bb = Bsm + (buf ^ 1) * B_BUF + boff;
            bb[0]  = rb0.x; bb[8]  = rb0.y; bb[16] = rb0.z; bb[24] = rb0.w;
            bb[32] = rb1.x; bb[40] = rb1.y; bb[48] = rb1.z; bb[56] = rb1.w;
        }
        __syncthreads();
        buf ^= 1;
    }
}

#define MMA_PROLOG()                              \
    int t    = threadIdx.x;                       \
    int lane = t & 31;                            \
    int wid  = t >> 5;                            \
    int ar   = t >> 1;                            \
    int ac   = (t & 1) * 8;                       \
    int bkr  = t >> 4;                            \
    int bc   = (t & 15) * 8;                      \
    int g    = lane >> 2;                         \
    int c    = lane & 3;                          \
    int m0base = (wid & 1) * 64;                  \
    int n0base = (wid >> 1) * 32;                 \
    __shared__ float Asm[2 * A_BUF];              \
    __shared__ float Bsm[2 * B_BUF];              \
    float acc[16][4];                             \
    _Pragma("unroll")                             \
    for (int _i = 0; _i < 16; _i++)               \
        for (int _j = 0; _j < 4; _j++) acc[_i][_j] = 0.f;

// ---------------------------------------------------------------------------
// Weight tf32 pre-round: out[i] = round_tf32(in[i]), float4 vectorized
// ---------------------------------------------------------------------------
__global__ void round4_kernel(const float* __restrict__ in, float* __restrict__ outp, int n4) {
    int i = blockIdx.x * 256 + threadIdx.x;
    if (i >= n4) return;
    float4 v = ((const float4*)in)[i];
    v.x = roundtf(v.x); v.y = roundtf(v.y); v.z = roundtf(v.z); v.w = roundtf(v.w);
    ((float4*)outp)[i] = v;
}

// ---------------------------------------------------------------------------
// Fused QKV projection: grid (Tn/128, Dn/128, 3)
// ---------------------------------------------------------------------------
__global__ void __launch_bounds__(256, 2)
qkv_gemm(const float* __restrict__ h1) {
    const float* W = (blockIdx.z == 0) ? g_wqr : (blockIdx.z == 1) ? g_wkr : g_wvr;
    float* C = (blockIdx.z == 0) ? g_q : (blockIdx.z == 1) ? g_k : g_v;
    int bm = blockIdx.x * BM, bn = blockIdx.y * BN;
    MMA_PROLOG();
    gemm_core_frag(h1 + (size_t)(bm + ar) * Dn + ac,
                   W + (size_t)bkr * Dn + bn + bc,
                   Dn, Dn / BK, acc, Asm, Bsm, t, lane, m0base, n0base);
    #pragma unroll
    for (int mf = 0; mf < 4; mf++) {
        int r0 = bm + m0base + mf * 16 + g;
        #pragma unroll
        for (int nf = 0; nf < 4; nf++) {
            int cb = bn + n0base + nf * 8 + c * 2;
            float* cc = acc[mf * 4 + nf];
            *(float2*)(C + (size_t)r0 * Dn + cb)       = make_float2(cc[0], cc[1]);
            *(float2*)(C + (size_t)(r0 + 8) * Dn + cb) = make_float2(cc[2], cc[3]);
        }
    }
}

// ---------------------------------------------------------------------------
// O projection + residual: x1 = x + att @ wo.  grid (Tn/128, Dn/128)
// ---------------------------------------------------------------------------
__global__ void __launch_bounds__(256, 2)
oproj_gemm(const float* __restrict__ x) {
    int bm = blockIdx.x * BM, bn = blockIdx.y * BN;
    MMA_PROLOG();
    gemm_core_frag(g_att + (size_t)(bm + ar) * Dn + ac,
                   g_wor + (size_t)bkr * Dn + bn + bc,
                   Dn, Dn / BK, acc, Asm, Bsm, t, lane, m0base, n0base);
    #pragma unroll
    for (int mf = 0; mf < 4; mf++) {
        int r0 = bm + m0base + mf * 16 + g;
        #pragma unroll
        for (int nf = 0; nf < 4; nf++) {
            int cb = bn + n0base + nf * 8 + c * 2;
            float* cc = acc[mf * 4 + nf];
            size_t p0 = (size_t)r0 * Dn + cb;
            size_t p1 = (size_t)(r0 + 8) * Dn + cb;
            float2 x0 = *(const float2*)(x + p0);
            float2 x1v = *(const float2*)(x + p1);
            *(float2*)(g_x1 + p0) = make_float2(x0.x + cc[0], x0.y + cc[1]);
            *(float2*)(g_x1 + p1) = make_float2(x1v.x + cc[2], x1v.y + cc[3]);
        }
    }
}

// ---------------------------------------------------------------------------
// MoE FFN1: gathered rows, gelu(X@w1[e] + b1[e]) -> g_mid (tf32-rounded)
// grid (Tn/128, Fn/128, E)
// ---------------------------------------------------------------------------
__global__ void __launch_bounds__(256, 2)
moe_ffn1(const float* __restrict__ b1) {
    int e = blockIdx.z;
    int cnt = g_counts[e];
    int bm = blockIdx.x * BM;
    if (bm >= cnt) return;
    int off = g_offsets[e];
    int bn = blockIdx.y * BN;
    MMA_PROLOG();
    int arow = bm + ar; if (arow >= cnt) arow = cnt - 1;
    int tok = g_slot2tok[off + arow];
    gemm_core_frag(g_h2r + (size_t)tok * Dn + ac,
                   g_w1r + (size_t)e * Dn * Fn + (size_t)bkr * Fn + bn + bc,
                   Fn, Dn / BK, acc, Asm, Bsm, t, lane, m0base, n0base);
    #pragma unroll
    for (int mf = 0; mf < 4; mf++) {
        int r0 = bm + m0base + mf * 16 + g;
        int r1 = r0 + 8;
        #pragma unroll
        for (int nf = 0; nf < 4; nf++) {
            int cb = bn + n0base + nf * 8 + c * 2;
            float bv0 = b1[e * Fn + cb], bv1 = b1[e * Fn + cb + 1];
            float* cc = acc[mf * 4 + nf];
            if (r0 < cnt)
                *(float2*)(g_mid + (size_t)(off + r0) * Fn + cb) =
                    make_float2(roundtf(gelu_tanh(cc[0] + bv0)),
                                roundtf(gelu_tanh(cc[1] + bv1)));
            if (r1 < cnt)
                *(float2*)(g_mid + (size_t)(off + r1) * Fn + cb) =
                    make_float2(roundtf(gelu_tanh(cc[2] + bv0)),
                                roundtf(gelu_tanh(cc[3] + bv1)));
        }
    }
}

// ---------------------------------------------------------------------------
// MoE FFN2: mid@w2[e] + b2[e] -> g_eout.  grid (Tn/128, Dn/128, E)
// ---------------------------------------------------------------------------
__global__ void __launch_bounds__(256, 2)
moe_ffn2(const float* __restrict__ b2) {
    int e = blockIdx.z;
    int cnt = g_counts[e];
    int bm = blockIdx.x * BM;
    if (bm >= cnt) return;
    int off = g_offsets[e];
    int bn = blockIdx.y * BN;
    MMA_PROLOG();
    int arow = bm + ar; if (arow >= cnt) arow = cnt - 1;
    gemm_core_frag(g_mid + (size_t)(off + arow) * Fn + ac,
                   g_w2r + (size_t)e * Fn * Dn + (size_t)bkr * Dn + bn + bc,
                   Dn, Fn / BK, acc, Asm, Bsm, t, lane, m0base, n0base);
    #pragma unroll
    for (int mf = 0; mf < 4; mf++) {
        int r0 = bm + m0base + mf * 16 + g;
        int r1 = r0 + 8;
        #pragma unroll
        for (int nf = 0; nf < 4; nf++) {
            int cb = bn + n0base + nf * 8 + c * 2;
            float bv0 = b2[e * Dn + cb], bv1 = b2[e * Dn + cb + 1];
            float* cc = acc[mf * 4 + nf];
            if (r0 < cnt)
                *(float2*)(g_eout + (size_t)(off + r0) * Dn + cb) =
                    make_float2(cc[0] + bv0, cc[1] + bv1);
            if (r1 < cnt)
                *(float2*)(g_eout + (size_t)(off + r1) * Dn + cb) =
                    make_float2(cc[2] + bv0, cc[3] + bv1);
        }
    }
}

// ---------------------------------------------------------------------------
// LayerNorm: one block per token, 256 threads, D=768 (3 elems/thread).
// out = tf32-rounded LN (feeds GEMM A); out2 (optional) = exact LN (routing).
// ---------------------------------------------------------------------------
__global__ void ln_kernel(const float* __restrict__ x,
                          const float* __restrict__ g,
                          const float* __restrict__ b,
                          float* __restrict__ out,
                          float* __restrict__ out2) {
    int t = blockIdx.x;
    const float* row = x + (size_t)t * Dn;
    int tid = threadIdx.x;
    float v0 = row[tid], v1 = row[tid + 256], v2 = row[tid + 512];
    float s  = v0 + v1 + v2;
    float ss = v0 * v0 + v1 * v1 + v2 * v2;
    #pragma unroll
    for (int o = 16; o; o >>= 1) {
        s  += __shfl_down_sync(0xffffffffu, s, o);
        ss += __shfl_down_sync(0xffffffffu, ss, o);
    }
    __shared__ float rs[8], rss[8];
    __shared__ float mu_s, rstd_s;
    int w = tid >> 5, l = tid & 31;
    if (l == 0) { rs[w] = s; rss[w] = ss; }
    __syncthreads();
    if (tid == 0) {
        float S = 0.f, SS = 0.f;
        #pragma unroll
        for (int i = 0; i < 8; i++) { S += rs[i]; SS += rss[i]; }
        float mu  = S / (float)Dn;
        float var = SS / (float)Dn - mu * mu;
        mu_s = mu; rstd_s = rsqrtf(var + 1e-5f);
    }
    __syncthreads();
    float mu = mu_s, rstd = rstd_s;
    float* orow = out + (size_t)t * Dn;
    float e0 = (v0 - mu) * rstd * g[tid]       + b[tid];
    float e1 = (v1 - mu) * rstd * g[tid + 256] + b[tid + 256];
    float e2 = (v2 - mu) * rstd * g[tid + 512] + b[tid + 512];
    orow[tid]       = roundtf(e0);
    orow[tid + 256] = roundtf(e1);
    orow[tid + 512] = roundtf(e2);
    if (out2) {
        float* xrow = out2 + (size_t)t * Dn;
        xrow[tid] = e0; xrow[tid + 256] = e1; xrow[tid + 512] = e2;
    }
}

// ---------------------------------------------------------------------------
// Flash-style attention: grid (S/128, H, B), 128 threads; one thread = one q row.
// Output tf32-rounded (feeds oproj A).
// ---------------------------------------------------------------------------
__global__ void __launch_bounds__(128)
attn_kernel(const float* __restrict__ q, const float* __restrict__ k,
            const float* __restrict__ v, float* __restrict__ o_out) {
    const int KT = 32;
    int h = blockIdx.y, b = blockIdx.z;
    int tid = threadIdx.x;
    int qrow = b * Sn + blockIdx.x * 128 + tid;
    const float* qptr = q + (size_t)qrow * Dn + h * DHn;
    float qreg[64];
    #pragma unroll
    for (int d = 0; d < 64; d++) qreg[d] = qptr[d] * 0.125f;  // 1/sqrt(64)
    float oacc[64];
    #pragma unroll
    for (int d = 0; d < 64; d++) oacc[d] = 0.f;
    float m = -1e30f, lsum = 0.f;

    __shared__ float Ks[KT][64], Vs[KT][64];
    for (int k0 = 0; k0 < Sn; k0 += KT) {
        for (int i = tid; i < KT * 64; i += 128) {
            int r = i >> 6, ccol = i & 63;
            size_t src = (size_t)(b * Sn + k0 + r) * Dn + h * DHn + ccol;
            Ks[r][ccol] = k[src];
            Vs[r][ccol] = v[src];
        }
        __syncthreads();
        float sv[KT];
        float smax = -1e30f;
        #pragma unroll
        for (int j = 0; j < KT; j++) {
            float s = 0.f;
            #pragma unroll
            for (int d = 0; d < 64; d++) s += qreg[d] * Ks[j][d];
            sv[j] = s;
            smax = fmaxf(smax, s);
        }
        float mnew = fmaxf(m, smax);
        float alpha = expf(m - mnew);
        float psum = 0.f;
        #pragma unroll
        for (int j = 0; j < KT; j++) { float p = expf(sv[j] - mnew); sv[j] = p; psum += p; }
        lsum = lsum * alpha + psum;
        #pragma unroll
        for (int d = 0; d < 64; d++) {
            float a = 0.f;
            #pragma unroll
            for (int j = 0; j < KT; j++) a += sv[j] * Vs[j][d];
            oacc[d] = oacc[d] * alpha + a;
        }
        m = mnew;
        __syncthreads();
    }
    float inv = 1.0f / lsum;
    float* op = o_out + (size_t)qrow * Dn + h * DHn;
    #pragma unroll
    for (int d = 0; d < 64; d++) op[d] = roundtf(oacc[d] * inv);
}

// ---------------------------------------------------------------------------
// MoE routing (reads EXACT h2 + exact gate_w: selection identical to reference)
// ---------------------------------------------------------------------------
__global__ void zero_counts_kernel() {
    if (threadIdx.x < En) g_counts[threadIdx.x] = 0;
}

__global__ void routing_kernel(const float* __restrict__ h2,
                               const float* __restrict__ gate_w,
                               const float* __restrict__ gate_b,
                               const float* __restrict__ bias_e) {
    int t = blockIdx.x;
    int wid = threadIdx.x >> 5, lane = threadIdx.x & 31;
    __shared__ float logit[En];
    float s = 0.f;
    const float* row = h2 + (size_t)t * Dn;
    for (int d = lane; d < Dn; d += 32) s += row[d] * gate_w[d * En + wid];
    #pragma unroll
    for (int o = 16; o; o >>= 1) s += __shfl_down_sync(0xffffffffu, s, o);
    if (lane == 0) logit[wid] = s + gate_b[wid];   // TAU = 1
    __syncthreads();
    if (threadIdx.x == 0) {
        float sel[En];
        #pragma unroll
        for (int e = 0; e < En; e++) sel[e] = logit[e] + bias_e[e];
        int i0 = 0;
        #pragma unroll
        for (int e = 1; e < En; e++) if (sel[e] > sel[i0]) i0 = e;
        int i1 = (i0 == 0) ? 1 : 0;
        #pragma unroll
        for (int e = 0; e < En; e++) if (e != i0 && sel[e] > sel[i1]) i1 = e;
        float l0 = logit[i0], l1 = logit[i1];
        float mm = fmaxf(l0, l1);
        float e0 = expf(l0 - mm), e1 = expf(l1 - mm);
        float inv = 1.0f / (e0 + e1);
        g_idx[t * 2] = i0;     g_idx[t * 2 + 1] = i1;
        g_gate[t * 2] = e0 * inv; g_gate[t * 2 + 1] = e1 * inv;
        g_pos[t * 2]     = atomicAdd(&g_counts[i0], 1);
        g_pos[t * 2 + 1] = atomicAdd(&g_counts[i1], 1);
    }
}

__global__ void offsets_kernel() {
    if (threadIdx.x == 0) {
        int acc = 0;
        for (int e = 0; e < En; e++) { g_offsets[e] = acc; acc += g_counts[e]; }
    }
}

__global__ void fill_slots_kernel() {
    int t = blockIdx.x * 256 + threadIdx.x;
    if (t >= Tn) return;
    #pragma unroll
    for (int kk = 0; kk < 2; kk++) {
        int e = g_idx[t * 2 + kk];
        int slot = g_offsets[e] + g_pos[t * 2 + kk];
        g_slotof[t * 2 + kk] = slot;
        g_slot2tok[slot] = t;
    }
}

// ---------------------------------------------------------------------------
// Final combine: out = x1 + g0*eout[slot0] + g1*eout[slot1]
// ---------------------------------------------------------------------------
__global__ void combine_kernel(const float* __restrict__ x1, float* __restrict__ out) {
    int t = blockIdx.x;
    int d = blockIdx.y * 256 + threadIdx.x;
    int s0 = g_slotof[t * 2], s1 = g_slotof[t * 2 + 1];
    float g0 = g_gate[t * 2], g1 = g_gate[t * 2 + 1];
    out[(size_t)t * Dn + d] = x1[(size_t)t * Dn + d]
                            + g0 * g_eout[(size_t)s0 * Dn + d]
                            + g1 * g_eout[(size_t)s1 * Dn + d];
}

// ---------------------------------------------------------------------------
// launch
// ---------------------------------------------------------------------------
extern "C" void kernel_launch(void* const* d_in, const int* in_sizes, int n_in,
                              void* d_out, int out_size) {
    const float* x      = (const float*)d_in[0];
    const float* wq     = (const float*)d_in[1];
    const float* wk     = (const float*)d_in[2];
    const float* wv     = (const float*)d_in[3];
    const float* wo     = (const float*)d_in[4];
    const float* ln1_g  = (const float*)d_in[5];
    const float* ln1_b  = (const float*)d_in[6];
    const float* ln2_g  = (const float*)d_in[7];
    const float* ln2_b  = (const float*)d_in[8];
    const float* gate_w = (const float*)d_in[9];
    const float* gate_b = (const float*)d_in[10];
    const float* bias_e = (const float*)d_in[11];
    const float* w1     = (const float*)d_in[12];
    const float* b1     = (const float*)d_in[13];
    const float* w2     = (const float*)d_in[14];
    const float* b2     = (const float*)d_in[15];
    float* out = (float*)d_out;

    float *h1, *qb, *kb, *vb, *att, *x1, *h2r, *h2x;
    float *wqr, *wkr, *wvr, *wor, *w1r, *w2r;
    cudaGetSymbolAddress((void**)&h1,  g_h1);
    cudaGetSymbolAddress((void**)&qb,  g_q);
    cudaGetSymbolAddress((void**)&kb,  g_k);
    cudaGetSymbolAddress((void**)&vb,  g_v);
    cudaGetSymbolAddress((void**)&att, g_att);
    cudaGetSymbolAddress((void**)&x1,  g_x1);
    cudaGetSymbolAddress((void**)&h2r, g_h2r);
    cudaGetSymbolAddress((void**)&h2x, g_h2x);
    cudaGetSymbolAddress((void**)&wqr, g_wqr);
    cudaGetSymbolAddress((void**)&wkr, g_wkr);
    cudaGetSymbolAddress((void**)&wvr, g_wvr);
    cudaGetSymbolAddress((void**)&wor, g_wor);
    cudaGetSymbolAddress((void**)&w1r, g_w1r);
    cudaGetSymbolAddress((void**)&w2r, g_w2r);

    // --- tf32 pre-round of weights ---
    const int DD4 = Dn * Dn / 4;                  // 147456
    const int W4  = En * Dn * Fn / 4;             // 4718592
    round4_kernel<<<(DD4 + 255) / 256, 256>>>(wq, wqr, DD4);
    round4_kernel<<<(DD4 + 255) / 256, 256>>>(wk, wkr, DD4);
    round4_kernel<<<(DD4 + 255) / 256, 256>>>(wv, wvr, DD4);
    round4_kernel<<<(DD4 + 255) / 256, 256>>>(wo, wor, DD4);
    round4_kernel<<<(W4 + 255) / 256, 256>>>(w1, w1r, W4);
    round4_kernel<<<(W4 + 255) / 256, 256>>>(w2, w2r, W4);

    // --- attention block ---
    ln_kernel<<<Tn, 256>>>(x, ln1_g, ln1_b, h1, nullptr);
    qkv_gemm<<<dim3(Tn / BM, Dn / BN, 3), 256>>>(h1);
    attn_kernel<<<dim3(Sn / 128, Hn, Bsz), 128>>>(qb, kb, vb, att);
    oproj_gemm<<<dim3(Tn / BM, Dn / BN), 256>>>(x);

    // --- MoE block ---
    ln_kernel<<<Tn, 256>>>(x1, ln2_g, ln2_b, h2r, h2x);
    zero_counts_kernel<<<1, 32>>>();
    routing_kernel<<<Tn, 256>>>(h2x, gate_w, gate_b, bias_e);
    offsets_kernel<<<1, 32>>>();
    fill_slots_kernel<<<Tn / 256, 256>>>();
    moe_ffn1<<<dim3(Tn / BM, Fn / BN, En), 256>>>(b1);
    moe_ffn2<<<dim3(Tn / BM, Dn / BN, En), 256>>>(b2);
    combine_kernel<<<dim3(Tn, Dn / 256), 256>>>(x1, out);
}

// round 12
// speedup vs baseline: 1.0826x; 1.0826x over previous
#include <cuda_runtime.h>
#include <math.h>
#include <stdint.h>

// ---- problem dims ----
#define Tn 4096      // B*S tokens
#define Dn 768
#define Hn 12
#define DHn 64
#define Sn 512
#define Bsz 8
#define En 8
#define Fn 3072
#define TOPK 2

#define BM 128
#define BN 128
#define BK 16
#define LDA 20    // A smem row stride (words); 20r mod 32 covers all banks -> ldmatrix conflict-free
#define LDB 136   // B smem row stride (words); 8c+g is a bank permutation

// ---- scratch (device globals: allocation-free per harness rules) ----
__device__ float g_h1[Tn * Dn];
__device__ float g_q[Tn * Dn];
__device__ float g_k[Tn * Dn];
__device__ float g_v[Tn * Dn];
__device__ float g_att[Tn * Dn];
__device__ float g_x1[Tn * Dn];
__device__ float g_h2r[Tn * Dn];                  // tf32-rounded (GEMM A)
__device__ float g_h2x[Tn * Dn];                  // exact (routing)
__device__ float g_mid[(size_t)Tn * TOPK * Fn];   // ~100 MB
__device__ float g_eout[Tn * TOPK * Dn];          // ~25 MB
// tf32-rounded weight copies
__device__ float g_wqr[Dn * Dn];
__device__ float g_wkr[Dn * Dn];
__device__ float g_wvr[Dn * Dn];
__device__ float g_wor[Dn * Dn];
__device__ float g_w1r[(size_t)En * Dn * Fn];     // 72 MB
__device__ float g_w2r[(size_t)En * Fn * Dn];     // 72 MB
__device__ int   g_idx[Tn * TOPK];
__device__ float g_gate[Tn * TOPK];
__device__ int   g_pos[Tn * TOPK];
__device__ int   g_slotof[Tn * TOPK];
__device__ int   g_slot2tok[Tn * TOPK];
__device__ int   g_counts[En];
__device__ int   g_offsets[En];

// ---- helpers ----
__device__ __forceinline__ float gelu_tanh(float x) {
    const float c = 0.7978845608028654f;   // sqrt(2/pi)
    float t = tanhf(c * (x + 0.044715f * x * x * x));
    return 0.5f * x * (1.0f + t);
}

__device__ __forceinline__ uint32_t f2tf(float x) {
    uint32_t r;
    asm("cvt.rna.tf32.f32 %0, %1;" : "=r"(r) : "f"(x));
    return r;
}
__device__ __forceinline__ float roundtf(float x) { return __uint_as_float(f2tf(x)); }

__device__ __forceinline__ void mma_tf32(float* cc,
    uint32_t a0, uint32_t a1, uint32_t a2, uint32_t a3,
    uint32_t b0, uint32_t b1) {
    asm volatile(
        "mma.sync.aligned.m16n8k8.row.col.f32.tf32.tf32.f32 "
        "{%0,%1,%2,%3},{%4,%5,%6,%7},{%8,%9},{%0,%1,%2,%3};"
        : "+f"(cc[0]), "+f"(cc[1]), "+f"(cc[2]), "+f"(cc[3])
        : "r"(a0), "r"(a1), "r"(a2), "r"(a3), "r"(b0), "r"(b1));
}

// ldmatrix x4: four 8x8 b16 tiles == four 8x4 b32 tiles.
// Thread fragment map (b32 view): row = lane/4, col = lane%4 -> exactly the
// m16n8k8.tf32 A fragment. Tile j addressed by lanes j*8..j*8+7; reg j <- tile j.
__device__ __forceinline__ void ldsm_x4(uint32_t& r0, uint32_t& r1,
                                        uint32_t& r2, uint32_t& r3, uint32_t addr) {
    asm volatile("ldmatrix.sync.aligned.m8n8.x4.shared.b16 {%0,%1,%2,%3}, [%4];"
                 : "=r"(r0), "=r"(r1), "=r"(r2), "=r"(r3) : "r"(addr));
}

__device__ __forceinline__ uint32_t sptr(const void* p) {
    return (uint32_t)__cvta_generic_to_shared(p);
}
#define CP16(s, g) asm volatile("cp.async.cg.shared.global [%0], [%1], 16;" :: "r"(s), "l"(g))
#define CPCOMMIT() asm volatile("cp.async.commit_group;")
#define CPWAIT1()  asm volatile("cp.async.wait_group 1;")
#define CPWAIT0()  asm volatile("cp.async.wait_group 0;")

// ---------------------------------------------------------------------------
// tf32 tensor-core GEMM core, cp.async pipeline + ldmatrix A-fragments.
// 128x128 tile, BK=16, 256 threads (8 warps), warp tile 64x32
// (4 Mfrags x 4 Nfrags of m16n8k8), fp32 accumulate.
// Operands PRE-ROUNDED to tf32 (raw copy; no cvt in hot loop).
// Smem: As[2][128][LDA] row-major [m][k]; Bs[2][16][LDB] [k][n].
// Stage (per thread, per K-tile): A row ar cols ac..ac+7 (2x cp16);
//                                 B row bkr cols bc..bc+7 (2x cp16).
// Compute: A = 1 ldmatrix.x4 per (mf,kb)  [8 per K-tile];
//          B = 2 scalar LDS per (nf,kb)    [16 per K-tile].
// ldmatrix lane addressing: lanes j*8..j*8+7 give the 8 row addrs of tile j:
//   tile0 rows m0..m0+7 k0..3, tile1 rows +8 k0..3, tile2 rows m0.. k4..7,
//   tile3 rows +8 k4..7  ->  {a0,a1,a2,a3} in PTX fragment order.
// ---------------------------------------------------------------------------
__device__ __forceinline__ void gemm_core_async(
    const float* __restrict__ arow,   // A base + (staging row)*lda
    const float* __restrict__ bcol,   // B base + bn + bc
    int ldb, int iters,
    float (&acc)[16][4],
    float (*As)[BM][LDA], float (*Bs)[BK][LDB],
    int ar, int ac, int bkr, int bc,
    int lane, int g, int c, int m0base, int n0base)
{
    uint32_t a_s0 = sptr(&As[0][ar][ac]);
    uint32_t a_s1 = sptr(&As[1][ar][ac]);
    uint32_t b_s0 = sptr(&Bs[0][bkr][bc]);
    uint32_t b_s1 = sptr(&Bs[1][bkr][bc]);
    const float* ag = arow + ac;
    const float* bg = bcol + (size_t)bkr * ldb;

    // ldmatrix per-lane source address (within buffer 0)
    int lrow = ((lane >> 3) & 1) * 8 + (lane & 7);   // row within m16 block
    int lcol = (lane >> 4) * 4;                      // k col group {0,4}
    uint32_t a_lm0 = sptr(&As[0][m0base + lrow][lcol]);
    uint32_t a_lm1 = sptr(&As[1][m0base + lrow][lcol]);

    CP16(a_s0, ag); CP16(a_s0 + 16, ag + 4);
    CP16(b_s0, bg); CP16(b_s0 + 16, bg + 4);
    CPCOMMIT();

    int buf = 0;
    for (int it = 0; it < iters; it++) {
        if (it + 1 < iters) {
            const float* ag2 = ag + (it + 1) * BK;
            const float* bg2 = bg + (size_t)(it + 1) * BK * ldb;
            uint32_t asn = buf ? a_s0 : a_s1;
            uint32_t bsn = buf ? b_s0 : b_s1;
            CP16(asn, ag2); CP16(asn + 16, ag2 + 4);
            CP16(bsn, bg2); CP16(bsn + 16, bg2 + 4);
            CPCOMMIT();
            CPWAIT1();
        } else {
            CPWAIT0();
        }
        __syncthreads();
        uint32_t albase = buf ? a_lm1 : a_lm0;
        #pragma unroll
        for (int kb = 0; kb < 2; kb++) {
            uint32_t bf[4][2];
            #pragma unroll
            for (int nf = 0; nf < 4; nf++) {
                int n0 = n0base + nf * 8 + g;
                bf[nf][0] = __float_as_uint(Bs[buf][kb * 8 + c][n0]);
                bf[nf][1] = __float_as_uint(Bs[buf][kb * 8 + c + 4][n0]);
            }
            #pragma unroll
            for (int mf = 0; mf < 4; mf++) {
                uint32_t fa0, fa1, fa2, fa3;
                ldsm_x4(fa0, fa1, fa2, fa3,
                        albase + (uint32_t)(mf * 16 * LDA * 4 + kb * 32));
                #pragma unroll
                for (int nf = 0; nf < 4; nf++)
                    mma_tf32(acc[mf * 4 + nf], fa0, fa1, fa2, fa3,
                             bf[nf][0], bf[nf][1]);
            }
        }
        __syncthreads();
        buf ^= 1;
    }
}

#define MMA_PROLOG()                              \
    int t    = threadIdx.x;                       \
    int lane = t & 31;                            \
    int wid  = t >> 5;                            \
    int ar   = t >> 1;                            \
    int ac   = (t & 1) * 8;                       \
    int bkr  = t >> 4;                            \
    int bc   = (t & 15) * 8;                      \
    int g    = lane >> 2;                         \
    int c    = lane & 3;                          \
    int m0base = (wid & 1) * 64;                  \
    int n0base = (wid >> 1) * 32;                 \
    __shared__ float As[2][BM][LDA];              \
    __shared__ float Bs[2][BK][LDB];              \
    float acc[16][4];                             \
    _Pragma("unroll")                             \
    for (int _i = 0; _i < 16; _i++)               \
        for (int _j = 0; _j < 4; _j++) acc[_i][_j] = 0.f;

// ---------------------------------------------------------------------------
// Weight tf32 pre-round: out[i] = round_tf32(in[i]), float4 vectorized
// ---------------------------------------------------------------------------
__global__ void round4_kernel(const float* __restrict__ in, float* __restrict__ outp, int n4) {
    int i = blockIdx.x * 256 + threadIdx.x;
    if (i >= n4) return;
    float4 v = ((const float4*)in)[i];
    v.x = roundtf(v.x); v.y = roundtf(v.y); v.z = roundtf(v.z); v.w = roundtf(v.w);
    ((float4*)outp)[i] = v;
}

// ---------------------------------------------------------------------------
// Fused QKV projection: grid (Tn/128, Dn/128, 3)
// ---------------------------------------------------------------------------
__global__ void __launch_bounds__(256, 2)
qkv_gemm(const float* __restrict__ h1) {
    const float* W = (blockIdx.z == 0) ? g_wqr : (blockIdx.z == 1) ? g_wkr : g_wvr;
    float* C = (blockIdx.z == 0) ? g_q : (blockIdx.z == 1) ? g_k : g_v;
    int bm = blockIdx.x * BM, bn = blockIdx.y * BN;
    MMA_PROLOG();
    gemm_core_async(h1 + (size_t)(bm + ar) * Dn,
                    W + bn + bc,
                    Dn, Dn / BK, acc, As, Bs, ar, ac, bkr, bc, lane, g, c, m0base, n0base);
    #pragma unroll
    for (int mf = 0; mf < 4; mf++) {
        int r0 = bm + m0base + mf * 16 + g;
        #pragma unroll
        for (int nf = 0; nf < 4; nf++) {
            int cb = bn + n0base + nf * 8 + c * 2;
            float* cc = acc[mf * 4 + nf];
            *(float2*)(C + (size_t)r0 * Dn + cb)       = make_float2(cc[0], cc[1]);
            *(float2*)(C + (size_t)(r0 + 8) * Dn + cb) = make_float2(cc[2], cc[3]);
        }
    }
}

// ---------------------------------------------------------------------------
// O projection + residual: x1 = x + att @ wo.  grid (Tn/128, Dn/128)
// ---------------------------------------------------------------------------
__global__ void __launch_bounds__(256, 2)
oproj_gemm(const float* __restrict__ x) {
    int bm = blockIdx.x * BM, bn = blockIdx.y * BN;
    MMA_PROLOG();
    gemm_core_async(g_att + (size_t)(bm + ar) * Dn,
                    g_wor + bn + bc,
                    Dn, Dn / BK, acc, As, Bs, ar, ac, bkr, bc, lane, g, c, m0base, n0base);
    #pragma unroll
    for (int mf = 0; mf < 4; mf++) {
        int r0 = bm + m0base + mf * 16 + g;
        #pragma unroll
        for (int nf = 0; nf < 4; nf++) {
            int cb = bn + n0base + nf * 8 + c * 2;
            float* cc = acc[mf * 4 + nf];
            size_t p0 = (size_t)r0 * Dn + cb;
            size_t p1 = (size_t)(r0 + 8) * Dn + cb;
            float2 x0 = *(const float2*)(x + p0);
            float2 x1v = *(const float2*)(x + p1);
            *(float2*)(g_x1 + p0) = make_float2(x0.x + cc[0], x0.y + cc[1]);
            *(float2*)(g_x1 + p1) = make_float2(x1v.x + cc[2], x1v.y + cc[3]);
        }
    }
}

// ---------------------------------------------------------------------------
// MoE FFN1: gathered rows, gelu(X@w1[e] + b1[e]) -> g_mid (tf32-rounded)
// grid (Tn/128, Fn/128, E)
// ---------------------------------------------------------------------------
__global__ void __launch_bounds__(256, 2)
moe_ffn1(const float* __restrict__ b1) {
    int e = blockIdx.z;
    int cnt = g_counts[e];
    int bm = blockIdx.x * BM;
    if (bm >= cnt) return;
    int off = g_offsets[e];
    int bn = blockIdx.y * BN;
    MMA_PROLOG();
    int arow = bm + ar; if (arow >= cnt) arow = cnt - 1;
    int tok = g_slot2tok[off + arow];
    gemm_core_async(g_h2r + (size_t)tok * Dn,
                    g_w1r + (size_t)e * Dn * Fn + bn + bc,
                    Fn, Dn / BK, acc, As, Bs, ar, ac, bkr, bc, lane, g, c, m0base, n0base);
    #pragma unroll
    for (int mf = 0; mf < 4; mf++) {
        int r0 = bm + m0base + mf * 16 + g;
        int r1 = r0 + 8;
        #pragma unroll
        for (int nf = 0; nf < 4; nf++) {
            int cb = bn + n0base + nf * 8 + c * 2;
            float bv0 = b1[e * Fn + cb], bv1 = b1[e * Fn + cb + 1];
            float* cc = acc[mf * 4 + nf];
            if (r0 < cnt)
                *(float2*)(g_mid + (size_t)(off + r0) * Fn + cb) =
                    make_float2(roundtf(gelu_tanh(cc[0] + bv0)),
                                roundtf(gelu_tanh(cc[1] + bv1)));
            if (r1 < cnt)
                *(float2*)(g_mid + (size_t)(off + r1) * Fn + cb) =
                    make_float2(roundtf(gelu_tanh(cc[2] + bv0)),
                                roundtf(gelu_tanh(cc[3] + bv1)));
        }
    }
}

// ---------------------------------------------------------------------------
// MoE FFN2: mid@w2[e] + b2[e] -> g_eout.  grid (Tn/128, Dn/128, E)
// ---------------------------------------------------------------------------
__global__ void __launch_bounds__(256, 2)
moe_ffn2(const float* __restrict__ b2) {
    int e = blockIdx.z;
    int cnt = g_counts[e];
    int bm = blockIdx.x * BM;
    if (bm >= cnt) return;
    int off = g_offsets[e];
    int bn = blockIdx.y * BN;
    MMA_PROLOG();
    int arow = bm + ar; if (arow >= cnt) arow = cnt - 1;
    gemm_core_async(g_mid + (size_t)(off + arow) * Fn,
                    g_w2r + (size_t)e * Fn * Dn + bn + bc,
                    Dn, Fn / BK, acc, As, Bs, ar, ac, bkr, bc, lane, g, c, m0base, n0base);
    #pragma unroll
    for (int mf = 0; mf < 4; mf++) {
        int r0 = bm + m0base + mf * 16 + g;
        int r1 = r0 + 8;
        #pragma unroll
        for (int nf = 0; nf < 4; nf++) {
            int cb = bn + n0base + nf * 8 + c * 2;
            float bv0 = b2[e * Dn + cb], bv1 = b2[e * Dn + cb + 1];
            float* cc = acc[mf * 4 + nf];
            if (r0 < cnt)
                *(float2*)(g_eout + (size_t)(off + r0) * Dn + cb) =
                    make_float2(cc[0] + bv0, cc[1] + bv1);
            if (r1 < cnt)
                *(float2*)(g_eout + (size_t)(off + r1) * Dn + cb) =
                    make_float2(cc[2] + bv0, cc[3] + bv1);
        }
    }
}

// ---------------------------------------------------------------------------
// LayerNorm: one block per token, 256 threads, D=768 (3 elems/thread).
// out = tf32-rounded LN (feeds GEMM A); out2 (optional) = exact LN (routing).
// ---------------------------------------------------------------------------
__global__ void ln_kernel(const float* __restrict__ x,
                          const float* __restrict__ g,
                          const float* __restrict__ b,
                          float* __restrict__ out,
                          float* __restrict__ out2) {
    int t = blockIdx.x;
    const float* row = x + (size_t)t * Dn;
    int tid = threadIdx.x;
    float v0 = row[tid], v1 = row[tid + 256], v2 = row[tid + 512];
    float s  = v0 + v1 + v2;
    float ss = v0 * v0 + v1 * v1 + v2 * v2;
    #pragma unroll
    for (int o = 16; o; o >>= 1) {
        s  += __shfl_down_sync(0xffffffffu, s, o);
        ss += __shfl_down_sync(0xffffffffu, ss, o);
    }
    __shared__ float rs[8], rss[8];
    __shared__ float mu_s, rstd_s;
    int w = tid >> 5, l = tid & 31;
    if (l == 0) { rs[w] = s; rss[w] = ss; }
    __syncthreads();
    if (tid == 0) {
        float S = 0.f, SS = 0.f;
        #pragma unroll
        for (int i = 0; i < 8; i++) { S += rs[i]; SS += rss[i]; }
        float mu  = S / (float)Dn;
        float var = SS / (float)Dn - mu * mu;
        mu_s = mu; rstd_s = rsqrtf(var + 1e-5f);
    }
    __syncthreads();
    float mu = mu_s, rstd = rstd_s;
    float* orow = out + (size_t)t * Dn;
    float e0 = (v0 - mu) * rstd * g[tid]       + b[tid];
    float e1 = (v1 - mu) * rstd * g[tid + 256] + b[tid + 256];
    float e2 = (v2 - mu) * rstd * g[tid + 512] + b[tid + 512];
    orow[tid]       = roundtf(e0);
    orow[tid + 256] = roundtf(e1);
    orow[tid + 512] = roundtf(e2);
    if (out2) {
        float* xrow = out2 + (size_t)t * Dn;
        xrow[tid] = e0; xrow[tid + 256] = e1; xrow[tid + 512] = e2;
    }
}

// ---------------------------------------------------------------------------
// Flash-style attention: grid (S/128, H, B), 128 threads; one thread = one q row.
// Output tf32-rounded (feeds oproj A).
// ---------------------------------------------------------------------------
__global__ void __launch_bounds__(128)
attn_kernel(const float* __restrict__ q, const float* __restrict__ k,
            const float* __restrict__ v, float* __restrict__ o_out) {
    const int KT = 32;
    int h = blockIdx.y, b = blockIdx.z;
    int tid = threadIdx.x;
    int qrow = b * Sn + blockIdx.x * 128 + tid;
    const float* qptr = q + (size_t)qrow * Dn + h * DHn;
    float qreg[64];
    #pragma unroll
    for (int d = 0; d < 64; d++) qreg[d] = qptr[d] * 0.125f;  // 1/sqrt(64)
    float oacc[64];
    #pragma unroll
    for (int d = 0; d < 64; d++) oacc[d] = 0.f;
    float m = -1e30f, lsum = 0.f;

    __shared__ float Ks[KT][64], Vs[KT][64];
    for (int k0 = 0; k0 < Sn; k0 += KT) {
        for (int i = tid; i < KT * 64; i += 128) {
            int r = i >> 6, ccol = i & 63;
            size_t src = (size_t)(b * Sn + k0 + r) * Dn + h * DHn + ccol;
            Ks[r][ccol] = k[src];
            Vs[r][ccol] = v[src];
        }
        __syncthreads();
        float sv[KT];
        float smax = -1e30f;
        #pragma unroll
        for (int j = 0; j < KT; j++) {
            float s = 0.f;
            #pragma unroll
            for (int d = 0; d < 64; d++) s += qreg[d] * Ks[j][d];
            sv[j] = s;
            smax = fmaxf(smax, s);
        }
        float mnew = fmaxf(m, smax);
        float alpha = expf(m - mnew);
        float psum = 0.f;
        #pragma unroll
        for (int j = 0; j < KT; j++) { float p = expf(sv[j] - mnew); sv[j] = p; psum += p; }
        lsum = lsum * alpha + psum;
        #pragma unroll
        for (int d = 0; d < 64; d++) {
            float a = 0.f;
            #pragma unroll
            for (int j = 0; j < KT; j++) a += sv[j] * Vs[j][d];
            oacc[d] = oacc[d] * alpha + a;
        }
        m = mnew;
        __syncthreads();
    }
    float inv = 1.0f / lsum;
    float* op = o_out + (size_t)qrow * Dn + h * DHn;
    #pragma unroll
    for (int d = 0; d < 64; d++) op[d] = roundtf(oacc[d] * inv);
}

// ---------------------------------------------------------------------------
// MoE routing (reads EXACT h2 + exact gate_w: selection identical to reference)
// ---------------------------------------------------------------------------
__global__ void zero_counts_kernel() {
    if (threadIdx.x < En) g_counts[threadIdx.x] = 0;
}

__global__ void routing_kernel(const float* __restrict__ h2,
                               const float* __restrict__ gate_w,
                               const float* __restrict__ gate_b,
                               const float* __restrict__ bias_e) {
    int t = blockIdx.x;
    int wid = threadIdx.x >> 5, lane = threadIdx.x & 31;
    __shared__ float logit[En];
    float s = 0.f;
    const float* row = h2 + (size_t)t * Dn;
    for (int d = lane; d < Dn; d += 32) s += row[d] * gate_w[d * En + wid];
    #pragma unroll
    for (int o = 16; o; o >>= 1) s += __shfl_down_sync(0xffffffffu, s, o);
    if (lane == 0) logit[wid] = s + gate_b[wid];   // TAU = 1
    __syncthreads();
    if (threadIdx.x == 0) {
        float sel[En];
        #pragma unroll
        for (int e = 0; e < En; e++) sel[e] = logit[e] + bias_e[e];
        int i0 = 0;
        #pragma unroll
        for (int e = 1; e < En; e++) if (sel[e] > sel[i0]) i0 = e;
        int i1 = (i0 == 0) ? 1 : 0;
        #pragma unroll
        for (int e = 0; e < En; e++) if (e != i0 && sel[e] > sel[i1]) i1 = e;
        float l0 = logit[i0], l1 = logit[i1];
        float mm = fmaxf(l0, l1);
        float e0 = expf(l0 - mm), e1 = expf(l1 - mm);
        float inv = 1.0f / (e0 + e1);
        g_idx[t * 2] = i0;     g_idx[t * 2 + 1] = i1;
        g_gate[t * 2] = e0 * inv; g_gate[t * 2 + 1] = e1 * inv;
        g_pos[t * 2]     = atomicAdd(&g_counts[i0], 1);
        g_pos[t * 2 + 1] = atomicAdd(&g_counts[i1], 1);
    }
}

__global__ void offsets_kernel() {
    if (threadIdx.x == 0) {
        int acc = 0;
        for (int e = 0; e < En; e++) { g_offsets[e] = acc; acc += g_counts[e]; }
    }
}

__global__ void fill_slots_kernel() {
    int t = blockIdx.x * 256 + threadIdx.x;
    if (t >= Tn) return;
    #pragma unroll
    for (int kk = 0; kk < 2; kk++) {
        int e = g_idx[t * 2 + kk];
        int slot = g_offsets[e] + g_pos[t * 2 + kk];
        g_slotof[t * 2 + kk] = slot;
        g_slot2tok[slot] = t;
    }
}

// ---------------------------------------------------------------------------
// Final combine: out = x1 + g0*eout[slot0] + g1*eout[slot1]
// ---------------------------------------------------------------------------
__global__ void combine_kernel(const float* __restrict__ x1, float* __restrict__ out) {
    int t = blockIdx.x;
    int d = blockIdx.y * 256 + threadIdx.x;
    int s0 = g_slotof[t * 2], s1 = g_slotof[t * 2 + 1];
    float g0 = g_gate[t * 2], g1 = g_gate[t * 2 + 1];
    out[(size_t)t * Dn + d] = x1[(size_t)t * Dn + d]
                            + g0 * g_eout[(size_t)s0 * Dn + d]
                            + g1 * g_eout[(size_t)s1 * Dn + d];
}

// ---------------------------------------------------------------------------
// launch
// ---------------------------------------------------------------------------
extern "C" void kernel_launch(void* const* d_in, const int* in_sizes, int n_in,
                              void* d_out, int out_size) {
    const float* x      = (const float*)d_in[0];
    const float* wq     = (const float*)d_in[1];
    const float* wk     = (const float*)d_in[2];
    const float* wv     = (const float*)d_in[3];
    const float* wo     = (const float*)d_in[4];
    const float* ln1_g  = (const float*)d_in[5];
    const float* ln1_b  = (const float*)d_in[6];
    const float* ln2_g  = (const float*)d_in[7];
    const float* ln2_b  = (const float*)d_in[8];
    const float* gate_w = (const float*)d_in[9];
    const float* gate_b = (const float*)d_in[10];
    const float* bias_e = (const float*)d_in[11];
    const float* w1     = (const float*)d_in[12];
    const float* b1     = (const float*)d_in[13];
    const float* w2     = (const float*)d_in[14];
    const float* b2     = (const float*)d_in[15];
    float* out = (float*)d_out;

    float *h1, *qb, *kb, *vb, *att, *x1, *h2r, *h2x;
    float *wqr, *wkr, *wvr, *wor, *w1r, *w2r;
    cudaGetSymbolAddress((void**)&h1,  g_h1);
    cudaGetSymbolAddress((void**)&qb,  g_q);
    cudaGetSymbolAddress((void**)&kb,  g_k);
    cudaGetSymbolAddress((void**)&vb,  g_v);
    cudaGetSymbolAddress((void**)&att, g_att);
    cudaGetSymbolAddress((void**)&x1,  g_x1);
    cudaGetSymbolAddress((void**)&h2r, g_h2r);
    cudaGetSymbolAddress((void**)&h2x, g_h2x);
    cudaGetSymbolAddress((void**)&wqr, g_wqr);
    cudaGetSymbolAddress((void**)&wkr, g_wkr);
    cudaGetSymbolAddress((void**)&wvr, g_wvr);
    cudaGetSymbolAddress((void**)&wor, g_wor);
    cudaGetSymbolAddress((void**)&w1r, g_w1r);
    cudaGetSymbolAddress((void**)&w2r, g_w2r);

    // --- tf32 pre-round of weights ---
    const int DD4 = Dn * Dn / 4;                  // 147456
    const int W4  = En * Dn * Fn / 4;             // 4718592
    round4_kernel<<<(DD4 + 255) / 256, 256>>>(wq, wqr, DD4);
    round4_kernel<<<(DD4 + 255) / 256, 256>>>(wk, wkr, DD4);
    round4_kernel<<<(DD4 + 255) / 256, 256>>>(wv, wvr, DD4);
    round4_kernel<<<(DD4 + 255) / 256, 256>>>(wo, wor, DD4);
    round4_kernel<<<(W4 + 255) / 256, 256>>>(w1, w1r, W4);
    round4_kernel<<<(W4 + 255) / 256, 256>>>(w2, w2r, W4);

    // --- attention block ---
    ln_kernel<<<Tn, 256>>>(x, ln1_g, ln1_b, h1, nullptr);
    qkv_gemm<<<dim3(Tn / BM, Dn / BN, 3), 256>>>(h1);
    attn_kernel<<<dim3(Sn / 128, Hn, Bsz), 128>>>(qb, kb, vb, att);
    oproj_gemm<<<dim3(Tn / BM, Dn / BN), 256>>>(x);

    // --- MoE block ---
    ln_kernel<<<Tn, 256>>>(x1, ln2_g, ln2_b, h2r, h2x);
    zero_counts_kernel<<<1, 32>>>();
    routing_kernel<<<Tn, 256>>>(h2x, gate_w, gate_b, bias_e);
    offsets_kernel<<<1, 32>>>();
    fill_slots_kernel<<<Tn / 256, 256>>>();
    moe_ffn1<<<dim3(Tn / BM, Fn / BN, En), 256>>>(b1);
    moe_ffn2<<<dim3(Tn / BM, Dn / BN, En), 256>>>(b2);
    combine_kernel<<<dim3(Tn, Dn / 256), 256>>>(x1, out);
}